// round 7
// baseline (speedup 1.0000x reference)
#include <cuda_runtime.h>
#include <math.h>

// Problem constants
#define N_   256
#define T_   1000
#define NO_  10
#define NS_  10
#define HID_ 64
#define G3_  192   // 3*HID
#define D_   20    // NO+NS

// Scratch: xproj [N*T,192], hidden states [N,T,64], global double accumulator.
__device__ float  g_xp[(size_t)N_ * T_ * G3_];
__device__ float  g_h[(size_t)N_ * T_ * HID_];
__device__ double g_acc;

__global__ void k_zero() { g_acc = 0.0; }

// ---- packed f32x2 helpers ----
#define FMA2(d, a, b, c) \
    asm("fma.rn.f32x2 %0, %1, %2, %3;" : "=l"(d) : "l"(a), "l"(b), "l"(c))
#define ADD2(d, a, b) \
    asm("add.rn.f32x2 %0, %1, %2;" : "=l"(d) : "l"(a), "l"(b))
#define PACK2(d, lo, hi) \
    asm("mov.b64 %0, {%1, %2};" : "=l"(d) : "f"(lo), "f"(hi))
#define UNPACK2(lo, hi, s) \
    asm("mov.b64 {%0, %1}, %2;" : "=f"(lo), "=f"(hi) : "l"(s))

__device__ __forceinline__ float sigmoidf_(float x) {
    return 1.0f / (1.0f + __expf(-x));
}
__device__ __forceinline__ float tanhf_(float x) {
    x = fminf(fmaxf(x, -15.0f), 15.0f);
    float e = __expf(2.0f * x);
    return (e - 1.0f) / (e + 1.0f);
}
__device__ __forceinline__ float softplusf_(float x) {
    float ax = fabsf(x);
    return fmaxf(x, 0.0f) + log1pf(__expf(-ax));
}

// ---------------------------------------------------------------------------
// Kernel 0: precompute input projections xp[nt][192] = concat(y,xhat)@Wi + bi
// ---------------------------------------------------------------------------
__global__ void __launch_bounds__(G3_) k_xp(
    const float* __restrict__ Yi, const float* __restrict__ Xh,
    const float* __restrict__ Wi, const float* __restrict__ bi)
{
    __shared__ float xs[16][D_];
    const int j = threadIdx.x;
    const int nt0 = blockIdx.x * 16;
    for (int i = j; i < 16 * D_; i += G3_) {
        int r = i / D_, d = i - r * D_;
        int nt = nt0 + r;
        xs[r][d] = (d < NO_) ? Yi[(size_t)nt * NO_ + d]
                             : Xh[(size_t)nt * NS_ + (d - NO_)];
    }
    float w[D_];
#pragma unroll
    for (int d = 0; d < D_; d++) w[d] = Wi[d * G3_ + j];
    const float b = bi[j];
    __syncthreads();
#pragma unroll
    for (int r = 0; r < 16; r++) {
        float a = b;
#pragma unroll
        for (int d = 0; d < D_; d++) a = fmaf(xs[r][d], w[d], a);
        g_xp[(size_t)(nt0 + r) * G3_ + j] = a;
    }
}

// ---------------------------------------------------------------------------
// Kernel 1: persistent GRU. TWO samples per CTA, 128 threads (4 warps):
//   threads [0,64)   = sample 2b   (warps 0,1 -> SMSP 0,1)
//   threads [64,128) = sample 2b+1 (warps 2,3 -> SMSP 2,3)
// One warp per SMSP, one CTA per SM (128 CTAs). Thread u owns ALL THREE
// gates of unit u of its sample; ONE barrier per step; xp prefetch dist 2.
// ---------------------------------------------------------------------------
struct XPre { float r, z, n; };

__device__ __forceinline__ XPre ld_xp(const float* base, int u) {
    XPre o;
    o.r = __ldg(base + u);
    o.z = __ldg(base + HID_ + u);
    o.n = __ldg(base + 2 * HID_ + u);
    return o;
}

__device__ __forceinline__ void gru_step(
    const float* __restrict__ sh_src, float* __restrict__ sh_dst,
    const unsigned long long* wr2, const unsigned long long* wz2,
    const unsigned long long* wn2,
    float bhR, float bhZ, float bhN,
    XPre xp, float& hreg, float* hb_t, int u)
{
    unsigned long long ar0 = 0ull, ar1 = 0ull;
    unsigned long long az0 = 0ull, az1 = 0ull;
    unsigned long long an0 = 0ull, an1 = 0ull;
    const ulonglong2* h2 = (const ulonglong2*)sh_src;
#pragma unroll
    for (int c = 0; c < HID_ / 4; c++) {
        ulonglong2 hv = h2[c];
        FMA2(ar0, hv.x, wr2[2 * c],     ar0);
        FMA2(ar1, hv.y, wr2[2 * c + 1], ar1);
        FMA2(az0, hv.x, wz2[2 * c],     az0);
        FMA2(az1, hv.y, wz2[2 * c + 1], az1);
        FMA2(an0, hv.x, wn2[2 * c],     an0);
        FMA2(an1, hv.y, wn2[2 * c + 1], an1);
    }
    unsigned long long sr, sz, sn;
    ADD2(sr, ar0, ar1);
    ADD2(sz, az0, az1);
    ADD2(sn, an0, an1);
    float rl, rh, zl, zh, nl, nh;
    UNPACK2(rl, rh, sr);
    UNPACK2(zl, zh, sz);
    UNPACK2(nl, nh, sn);
    float r  = sigmoidf_(xp.r + bhR + rl + rh);
    float z  = sigmoidf_(xp.z + bhZ + zl + zh);
    float hn = bhN + nl + nh;
    float nn = tanhf_(xp.n + r * hn);
    hreg = fmaf(z, hreg - nn, nn);       // (1-z)*nn + z*h
    sh_dst[u] = hreg;
    hb_t[u] = hreg;
    __syncthreads();
}

__global__ void __launch_bounds__(128, 1) k_gru(
    const float* __restrict__ Wh, const float* __restrict__ bh)
{
    __shared__ __align__(16) float sh_h[2][2][HID_];   // [sample][buf][unit]

    const int tid = threadIdx.x;
    const int s   = tid >> 6;            // sample slot within CTA (0/1)
    const int u   = tid & (HID_ - 1);    // unit id, 0..63
    const int n   = blockIdx.x * 2 + s;  // global sample

    // weights for columns u (r), 64+u (z), 128+u (n): 96 packed pairs
    unsigned long long wr2[HID_ / 2], wz2[HID_ / 2], wn2[HID_ / 2];
#pragma unroll
    for (int k = 0; k < HID_ / 2; k++) {
        float a, b;
        a = Wh[(2 * k) * G3_ + u];             b = Wh[(2 * k + 1) * G3_ + u];
        PACK2(wr2[k], a, b);
        a = Wh[(2 * k) * G3_ + HID_ + u];      b = Wh[(2 * k + 1) * G3_ + HID_ + u];
        PACK2(wz2[k], a, b);
        a = Wh[(2 * k) * G3_ + 2 * HID_ + u];  b = Wh[(2 * k + 1) * G3_ + 2 * HID_ + u];
        PACK2(wn2[k], a, b);
    }
    const float bhR = bh[u], bhZ = bh[HID_ + u], bhN = bh[2 * HID_ + u];

    const float* xpt = g_xp + (size_t)n * T_ * G3_;
    float*       hb  = g_h  + (size_t)n * T_ * HID_;

    float hreg = 0.0f;
    sh_h[s][0][u] = 0.0f;
    __syncthreads();

    // prefetch xp for t=0 and t=1
    XPre P0 = ld_xp(xpt, u);
    XPre P1 = ld_xp(xpt + G3_, u);

#pragma unroll 1
    for (int t = 0; t < T_; t += 2) {
        // step t (even): src buf 0, dst buf 1
        gru_step(sh_h[s][0], sh_h[s][1], wr2, wz2, wn2, bhR, bhZ, bhN,
                 P0, hreg, hb + (size_t)t * HID_, u);
        {   // prefetch t+2 (clamped; value unused when t+2>=T)
            int tn = (t + 2 < T_) ? (t + 2) : (T_ - 1);
            P0 = ld_xp(xpt + (size_t)tn * G3_, u);
        }
        // step t+1 (odd): src buf 1, dst buf 0
        gru_step(sh_h[s][1], sh_h[s][0], wr2, wz2, wn2, bhR, bhZ, bhN,
                 P1, hreg, hb + (size_t)(t + 1) * HID_, u);
        {   // prefetch t+3
            int tn = (t + 3 < T_) ? (t + 3) : (T_ - 1);
            P1 = ld_xp(xpt + (size_t)tn * G3_, u);
        }
    }
}

// ---------------------------------------------------------------------------
// Kernel 2: per-(n,t) log-likelihood. One thread per (n,t).
// ---------------------------------------------------------------------------
__global__ void __launch_bounds__(256) k_loglik(
    const float* __restrict__ Yi,
    const float* __restrict__ Cw,
    const float* __restrict__ H,
    const float* __restrict__ mu_w,
    const float* __restrict__ W_mu, const float* __restrict__ b_mu,
    const float* __restrict__ W_var, const float* __restrict__ b_var)
{
    __shared__ __align__(16) float sW[HID_ * 2 * NO_]; // [k][2q+s]: s=0 mu, s=1 var
    __shared__ float sH[NO_ * NS_];
    __shared__ float smw[NO_], sbm[NO_], sbv[NO_];
    __shared__ double sred[8];

    const int tid = threadIdx.x;
    for (int i = tid; i < HID_ * 2 * NO_; i += 256) {
        int k = i / (2 * NO_);
        int rr = i - k * 2 * NO_;
        int q = rr >> 1;
        sW[i] = (rr & 1) ? W_var[k * NO_ + q] : W_mu[k * NO_ + q];
    }
    if (tid < NO_ * NS_) sH[tid] = H[tid];
    if (tid < NO_) { smw[tid] = mu_w[tid]; sbm[tid] = b_mu[tid]; sbv[tid] = b_var[tid]; }
    __syncthreads();

    const int gid = blockIdx.x * 256 + tid;   // 0 .. N*T-1
    const int n   = gid / T_;
    const float* hp = g_h + (size_t)gid * HID_;

    float mu[NO_], vr[NO_];
#pragma unroll
    for (int q = 0; q < NO_; q++) { mu[q] = sbm[q]; vr[q] = sbv[q]; }

    const float4* hp4 = (const float4*)hp;
#pragma unroll
    for (int k4 = 0; k4 < HID_ / 4; k4++) {
        float4 hv = hp4[k4];
        float hx[4] = { hv.x, hv.y, hv.z, hv.w };
#pragma unroll
        for (int uu = 0; uu < 4; uu++) {
            const float4* w4 = (const float4*)&sW[(4 * k4 + uu) * 2 * NO_];
#pragma unroll
            for (int q2 = 0; q2 < NO_ / 2; q2++) {
                float4 w = w4[q2];
                mu[2 * q2]     = fmaf(hx[uu], w.x, mu[2 * q2]);
                vr[2 * q2]     = fmaf(hx[uu], w.y, vr[2 * q2]);
                mu[2 * q2 + 1] = fmaf(hx[uu], w.z, mu[2 * q2 + 1]);
                vr[2 * q2 + 1] = fmaf(hx[uu], w.w, vr[2 * q2 + 1]);
            }
        }
    }
    float va[NO_];
#pragma unroll
    for (int q = 0; q < NO_; q++) va[q] = softplusf_(vr[q]);

    // e = y - (H mu + mu_w)
    const float* yp = Yi + (size_t)gid * NO_;
    float ee[NO_];
#pragma unroll
    for (int i = 0; i < NO_; i++) {
        float m = smw[i];
#pragma unroll
        for (int jq = 0; jq < NS_; jq++) m = fmaf(sH[i * NS_ + jq], mu[jq], m);
        ee[i] = yp[i] - m;
    }

    // A (lower) = H diag(va) H^T + Cw_n
    const float* cwp = Cw + (size_t)n * NO_ * NO_;
    float A[55];
#pragma unroll
    for (int i = 0; i < NO_; i++) {
        float hvi[NS_];
#pragma unroll
        for (int jq = 0; jq < NS_; jq++) hvi[jq] = sH[i * NS_ + jq] * va[jq];
#pragma unroll
        for (int k = 0; k <= i; k++) {
            float s = cwp[i * NO_ + k];
#pragma unroll
            for (int jq = 0; jq < NS_; jq++) s = fmaf(hvi[jq], sH[k * NS_ + jq], s);
            A[i * (i + 1) / 2 + k] = s;
        }
    }

    // In-place Cholesky; logdet accumulated as sum log(d^2)
    float dinv[NO_];
    float logdet = 0.0f;
#pragma unroll
    for (int k = 0; k < NO_; k++) {
        float s = A[k * (k + 1) / 2 + k];
#pragma unroll
        for (int jq = 0; jq < k; jq++) {
            float l = A[k * (k + 1) / 2 + jq];
            s = fmaf(-l, l, s);
        }
        logdet += logf(s);
        float d = sqrtf(s);
        float di = 1.0f / d;
        dinv[k] = di;
#pragma unroll
        for (int i = k + 1; i < NO_; i++) {
            float s2 = A[i * (i + 1) / 2 + k];
#pragma unroll
            for (int jq = 0; jq < k; jq++)
                s2 = fmaf(-A[i * (i + 1) / 2 + jq], A[k * (k + 1) / 2 + jq], s2);
            A[i * (i + 1) / 2 + k] = s2 * di;
        }
    }

    // quad = || L^{-1} e ||^2 (forward solve only)
    float quad = 0.0f;
#pragma unroll
    for (int i = 0; i < NO_; i++) {
        float s = ee[i];
#pragma unroll
        for (int jq = 0; jq < i; jq++) s = fmaf(-A[i * (i + 1) / 2 + jq], ee[jq], s);
        s *= dinv[i];
        ee[i] = s;
        quad = fmaf(s, s, quad);
    }

    double local = (double)logdet + (double)quad;
#pragma unroll
    for (int o = 16; o > 0; o >>= 1)
        local += __shfl_down_sync(0xffffffffu, local, o);
    if ((tid & 31) == 0) sred[tid >> 5] = local;
    __syncthreads();
    if (tid == 0) {
        double sum = 0.0;
#pragma unroll
        for (int w = 0; w < 8; w++) sum += sred[w];
        atomicAdd(&g_acc, sum);
    }
}

// ---------------------------------------------------------------------------
// Kernel 3: finalize scalar
// ---------------------------------------------------------------------------
__global__ void k_fin(float* out) {
    out[0] = (float)(-0.91893853320467274178
                     - 0.5 * g_acc / ((double)N_ * (double)T_ * (double)NO_));
}

extern "C" void kernel_launch(void* const* d_in, const int* in_sizes, int n_in,
                              void* d_out, int out_size) {
    const float* Yi    = (const float*)d_in[0];
    const float* Xh    = (const float*)d_in[1];
    const float* Cw    = (const float*)d_in[2];
    const float* H     = (const float*)d_in[3];
    const float* mu_w  = (const float*)d_in[4];
    const float* Wi    = (const float*)d_in[5];
    const float* Wh    = (const float*)d_in[6];
    const float* bi    = (const float*)d_in[7];
    const float* bh    = (const float*)d_in[8];
    const float* W_mu  = (const float*)d_in[9];
    const float* b_mu  = (const float*)d_in[10];
    const float* W_var = (const float*)d_in[11];
    const float* b_var = (const float*)d_in[12];

    k_zero<<<1, 1>>>();
    k_xp<<<(N_ * T_) / 16, G3_>>>(Yi, Xh, Wi, bi);
    k_gru<<<N_ / 2, 128>>>(Wh, bh);
    k_loglik<<<(N_ * T_) / 256, 256>>>(Yi, Cw, H, mu_w, W_mu, b_mu, W_var, b_var);
    k_fin<<<1, 1>>>((float*)d_out);
}

// round 10
// speedup vs baseline: 1.8914x; 1.8914x over previous
#include <cuda_runtime.h>
#include <math.h>

// Problem constants
#define N_   256
#define T_   1000
#define NO_  10
#define NS_  10
#define HID_ 64
#define G3_  192   // 3*HID
#define D_   20    // NO+NS

// Scratch: xproj [N*T,192], hidden states [N,T,64], global double accumulator.
__device__ float  g_xp[(size_t)N_ * T_ * G3_];
__device__ float  g_h[(size_t)N_ * T_ * HID_];
__device__ double g_acc;

__global__ void k_zero() { g_acc = 0.0; }
__global__ void k_pad() { }   // no-op: places k_gru at ncu capture slot (idx 3)

// ---- packed f32x2 helpers ----
#define FMA2(d, a, b, c) \
    asm("fma.rn.f32x2 %0, %1, %2, %3;" : "=l"(d) : "l"(a), "l"(b), "l"(c))
#define ADD2(d, a, b) \
    asm("add.rn.f32x2 %0, %1, %2;" : "=l"(d) : "l"(a), "l"(b))
#define PACK2(d, lo, hi) \
    asm("mov.b64 %0, {%1, %2};" : "=l"(d) : "f"(lo), "f"(hi))
#define UNPACK2(lo, hi, s) \
    asm("mov.b64 {%0, %1}, %2;" : "=f"(lo), "=f"(hi) : "l"(s))

// ---- fast activations via MUFU.TANH (sm_75+) ----
__device__ __forceinline__ float tanh_fast(float x) {
    float y;
    asm("tanh.approx.f32 %0, %1;" : "=f"(y) : "f"(x));
    return y;
}
__device__ __forceinline__ float sigmoid_fast(float x) {
    return fmaf(tanh_fast(0.5f * x), 0.5f, 0.5f);
}
__device__ __forceinline__ float softplusf_(float x) {
    float ax = fabsf(x);
    return fmaxf(x, 0.0f) + log1pf(__expf(-ax));
}

// ---------------------------------------------------------------------------
// Kernel 0: precompute input projections xp[nt][192] = concat(y,xhat)@Wi + bi
// ---------------------------------------------------------------------------
__global__ void __launch_bounds__(G3_) k_xp(
    const float* __restrict__ Yi, const float* __restrict__ Xh,
    const float* __restrict__ Wi, const float* __restrict__ bi)
{
    __shared__ float xs[16][D_];
    const int j = threadIdx.x;
    const int nt0 = blockIdx.x * 16;
    for (int i = j; i < 16 * D_; i += G3_) {
        int r = i / D_, d = i - r * D_;
        int nt = nt0 + r;
        xs[r][d] = (d < NO_) ? Yi[(size_t)nt * NO_ + d]
                             : Xh[(size_t)nt * NS_ + (d - NO_)];
    }
    float w[D_];
#pragma unroll
    for (int d = 0; d < D_; d++) w[d] = Wi[d * G3_ + j];
    const float b = bi[j];
    __syncthreads();
#pragma unroll
    for (int r = 0; r < 16; r++) {
        float a = b;
#pragma unroll
        for (int d = 0; d < D_; d++) a = fmaf(xs[r][d], w[d], a);
        g_xp[(size_t)(nt0 + r) * G3_ + j] = a;
    }
}

// ---------------------------------------------------------------------------
// Kernel 1: persistent GRU. One CTA per sample, 64 threads (2 warps).
// Thread u owns ALL THREE gates of unit u; ONE barrier per step;
// xp prefetched 2 steps ahead; activations via MUFU.TANH.
// ---------------------------------------------------------------------------
struct XPre { float r, z, n; };

__device__ __forceinline__ XPre ld_xp(const float* base, int u) {
    XPre o;
    o.r = __ldg(base + u);
    o.z = __ldg(base + HID_ + u);
    o.n = __ldg(base + 2 * HID_ + u);
    return o;
}

__device__ __forceinline__ void gru_step(
    const float* __restrict__ sh_src, float* __restrict__ sh_dst,
    const unsigned long long* wr2, const unsigned long long* wz2,
    const unsigned long long* wn2,
    float bhR, float bhZ, float bhN,
    XPre xp, float& hreg, float* hb_t, int u)
{
    unsigned long long ar0 = 0ull, ar1 = 0ull;
    unsigned long long az0 = 0ull, az1 = 0ull;
    unsigned long long an0 = 0ull, an1 = 0ull;
    const ulonglong2* h2 = (const ulonglong2*)sh_src;
#pragma unroll
    for (int c = 0; c < HID_ / 4; c++) {
        ulonglong2 hv = h2[c];
        FMA2(ar0, hv.x, wr2[2 * c],     ar0);
        FMA2(ar1, hv.y, wr2[2 * c + 1], ar1);
        FMA2(az0, hv.x, wz2[2 * c],     az0);
        FMA2(az1, hv.y, wz2[2 * c + 1], az1);
        FMA2(an0, hv.x, wn2[2 * c],     an0);
        FMA2(an1, hv.y, wn2[2 * c + 1], an1);
    }
    unsigned long long sr, sz, sn;
    ADD2(sr, ar0, ar1);
    ADD2(sz, az0, az1);
    ADD2(sn, an0, an1);
    float rl, rh, zl, zh, nl, nh;
    UNPACK2(rl, rh, sr);
    UNPACK2(zl, zh, sz);
    UNPACK2(nl, nh, sn);
    float r  = sigmoid_fast(xp.r + bhR + rl + rh);
    float z  = sigmoid_fast(xp.z + bhZ + zl + zh);
    float hn = bhN + nl + nh;
    float nn = tanh_fast(xp.n + r * hn);
    hreg = fmaf(z, hreg - nn, nn);       // (1-z)*nn + z*h
    sh_dst[u] = hreg;
    hb_t[u] = hreg;
    __syncthreads();
}

__global__ void __launch_bounds__(HID_, 2) k_gru(
    const float* __restrict__ Wh, const float* __restrict__ bh)
{
    __shared__ __align__(16) float sh_h[2][HID_];

    const int u = threadIdx.x;     // unit id, 0..63
    const int n = blockIdx.x;

    // weights for columns u (r), 64+u (z), 128+u (n): 96 packed pairs
    unsigned long long wr2[HID_ / 2], wz2[HID_ / 2], wn2[HID_ / 2];
#pragma unroll
    for (int k = 0; k < HID_ / 2; k++) {
        float a, b;
        a = Wh[(2 * k) * G3_ + u];             b = Wh[(2 * k + 1) * G3_ + u];
        PACK2(wr2[k], a, b);
        a = Wh[(2 * k) * G3_ + HID_ + u];      b = Wh[(2 * k + 1) * G3_ + HID_ + u];
        PACK2(wz2[k], a, b);
        a = Wh[(2 * k) * G3_ + 2 * HID_ + u];  b = Wh[(2 * k + 1) * G3_ + 2 * HID_ + u];
        PACK2(wn2[k], a, b);
    }
    const float bhR = bh[u], bhZ = bh[HID_ + u], bhN = bh[2 * HID_ + u];

    const float* xpt = g_xp + (size_t)n * T_ * G3_;
    float*       hb  = g_h  + (size_t)n * T_ * HID_;

    float hreg = 0.0f;
    sh_h[0][u] = 0.0f;
    __syncthreads();

    // prefetch xp for t=0 and t=1
    XPre P0 = ld_xp(xpt, u);
    XPre P1 = ld_xp(xpt + G3_, u);

#pragma unroll 1
    for (int t = 0; t < T_; t += 2) {
        // step t (even): src buf 0, dst buf 1
        gru_step(sh_h[0], sh_h[1], wr2, wz2, wn2, bhR, bhZ, bhN,
                 P0, hreg, hb + (size_t)t * HID_, u);
        {   // prefetch t+2 (clamped)
            int tn = (t + 2 < T_) ? (t + 2) : (T_ - 1);
            P0 = ld_xp(xpt + (size_t)tn * G3_, u);
        }
        // step t+1 (odd): src buf 1, dst buf 0
        gru_step(sh_h[1], sh_h[0], wr2, wz2, wn2, bhR, bhZ, bhN,
                 P1, hreg, hb + (size_t)(t + 1) * HID_, u);
        {   // prefetch t+3
            int tn = (t + 3 < T_) ? (t + 3) : (T_ - 1);
            P1 = ld_xp(xpt + (size_t)tn * G3_, u);
        }
    }
}

// ---------------------------------------------------------------------------
// Kernel 2: per-(n,t) log-likelihood. One thread per (n,t).
// ---------------------------------------------------------------------------
__global__ void __launch_bounds__(256) k_loglik(
    const float* __restrict__ Yi,
    const float* __restrict__ Cw,
    const float* __restrict__ H,
    const float* __restrict__ mu_w,
    const float* __restrict__ W_mu, const float* __restrict__ b_mu,
    const float* __restrict__ W_var, const float* __restrict__ b_var)
{
    __shared__ __align__(16) float sW[HID_ * 2 * NO_]; // [k][2q+s]: s=0 mu, s=1 var
    __shared__ float sH[NO_ * NS_];
    __shared__ float smw[NO_], sbm[NO_], sbv[NO_];
    __shared__ double sred[8];

    const int tid = threadIdx.x;
    for (int i = tid; i < HID_ * 2 * NO_; i += 256) {
        int k = i / (2 * NO_);
        int rr = i - k * 2 * NO_;
        int q = rr >> 1;
        sW[i] = (rr & 1) ? W_var[k * NO_ + q] : W_mu[k * NO_ + q];
    }
    if (tid < NO_ * NS_) sH[tid] = H[tid];
    if (tid < NO_) { smw[tid] = mu_w[tid]; sbm[tid] = b_mu[tid]; sbv[tid] = b_var[tid]; }
    __syncthreads();

    const int gid = blockIdx.x * 256 + tid;   // 0 .. N*T-1
    const int n   = gid / T_;
    const float* hp = g_h + (size_t)gid * HID_;

    float mu[NO_], vr[NO_];
#pragma unroll
    for (int q = 0; q < NO_; q++) { mu[q] = sbm[q]; vr[q] = sbv[q]; }

    const float4* hp4 = (const float4*)hp;
#pragma unroll
    for (int k4 = 0; k4 < HID_ / 4; k4++) {
        float4 hv = hp4[k4];
        float hx[4] = { hv.x, hv.y, hv.z, hv.w };
#pragma unroll
        for (int uu = 0; uu < 4; uu++) {
            const float4* w4 = (const float4*)&sW[(4 * k4 + uu) * 2 * NO_];
#pragma unroll
            for (int q2 = 0; q2 < NO_ / 2; q2++) {
                float4 w = w4[q2];
                mu[2 * q2]     = fmaf(hx[uu], w.x, mu[2 * q2]);
                vr[2 * q2]     = fmaf(hx[uu], w.y, vr[2 * q2]);
                mu[2 * q2 + 1] = fmaf(hx[uu], w.z, mu[2 * q2 + 1]);
                vr[2 * q2 + 1] = fmaf(hx[uu], w.w, vr[2 * q2 + 1]);
            }
        }
    }
    float va[NO_];
#pragma unroll
    for (int q = 0; q < NO_; q++) va[q] = softplusf_(vr[q]);

    // e = y - (H mu + mu_w)
    const float* yp = Yi + (size_t)gid * NO_;
    float ee[NO_];
#pragma unroll
    for (int i = 0; i < NO_; i++) {
        float m = smw[i];
#pragma unroll
        for (int jq = 0; jq < NS_; jq++) m = fmaf(sH[i * NS_ + jq], mu[jq], m);
        ee[i] = yp[i] - m;
    }

    // A (lower) = H diag(va) H^T + Cw_n
    const float* cwp = Cw + (size_t)n * NO_ * NO_;
    float A[55];
#pragma unroll
    for (int i = 0; i < NO_; i++) {
        float hvi[NS_];
#pragma unroll
        for (int jq = 0; jq < NS_; jq++) hvi[jq] = sH[i * NS_ + jq] * va[jq];
#pragma unroll
        for (int k = 0; k <= i; k++) {
            float s = cwp[i * NO_ + k];
#pragma unroll
            for (int jq = 0; jq < NS_; jq++) s = fmaf(hvi[jq], sH[k * NS_ + jq], s);
            A[i * (i + 1) / 2 + k] = s;
        }
    }

    // In-place Cholesky; logdet accumulated as sum log(d^2)
    float dinv[NO_];
    float logdet = 0.0f;
#pragma unroll
    for (int k = 0; k < NO_; k++) {
        float s = A[k * (k + 1) / 2 + k];
#pragma unroll
        for (int jq = 0; jq < k; jq++) {
            float l = A[k * (k + 1) / 2 + jq];
            s = fmaf(-l, l, s);
        }
        logdet += logf(s);
        float d = sqrtf(s);
        float di = 1.0f / d;
        dinv[k] = di;
#pragma unroll
        for (int i = k + 1; i < NO_; i++) {
            float s2 = A[i * (i + 1) / 2 + k];
#pragma unroll
            for (int jq = 0; jq < k; jq++)
                s2 = fmaf(-A[i * (i + 1) / 2 + jq], A[k * (k + 1) / 2 + jq], s2);
            A[i * (i + 1) / 2 + k] = s2 * di;
        }
    }

    // quad = || L^{-1} e ||^2 (forward solve only)
    float quad = 0.0f;
#pragma unroll
    for (int i = 0; i < NO_; i++) {
        float s = ee[i];
#pragma unroll
        for (int jq = 0; jq < i; jq++) s = fmaf(-A[i * (i + 1) / 2 + jq], ee[jq], s);
        s *= dinv[i];
        ee[i] = s;
        quad = fmaf(s, s, quad);
    }

    double local = (double)logdet + (double)quad;
#pragma unroll
    for (int o = 16; o > 0; o >>= 1)
        local += __shfl_down_sync(0xffffffffu, local, o);
    if ((tid & 31) == 0) sred[tid >> 5] = local;
    __syncthreads();
    if (tid == 0) {
        double sum = 0.0;
#pragma unroll
        for (int w = 0; w < 8; w++) sum += sred[w];
        atomicAdd(&g_acc, sum);
    }
}

// ---------------------------------------------------------------------------
// Kernel 3: finalize scalar
// ---------------------------------------------------------------------------
__global__ void k_fin(float* out) {
    out[0] = (float)(-0.91893853320467274178
                     - 0.5 * g_acc / ((double)N_ * (double)T_ * (double)NO_));
}

extern "C" void kernel_launch(void* const* d_in, const int* in_sizes, int n_in,
                              void* d_out, int out_size) {
    const float* Yi    = (const float*)d_in[0];
    const float* Xh    = (const float*)d_in[1];
    const float* Cw    = (const float*)d_in[2];
    const float* H     = (const float*)d_in[3];
    const float* mu_w  = (const float*)d_in[4];
    const float* Wi    = (const float*)d_in[5];
    const float* Wh    = (const float*)d_in[6];
    const float* bi    = (const float*)d_in[7];
    const float* bh    = (const float*)d_in[8];
    const float* W_mu  = (const float*)d_in[9];
    const float* b_mu  = (const float*)d_in[10];
    const float* W_var = (const float*)d_in[11];
    const float* b_var = (const float*)d_in[12];

    k_zero<<<1, 1>>>();
    k_xp<<<(N_ * T_) / 16, G3_>>>(Yi, Xh, Wi, bi);
    k_pad<<<1, 1>>>();   // pad so k_gru sits at launch index 3 (ncu capture slot)
    k_gru<<<N_, HID_>>>(Wh, bh);
    k_loglik<<<(N_ * T_) / 256, 256>>>(Yi, Cw, H, mu_w, W_mu, b_mu, W_var, b_var);
    k_fin<<<1, 1>>>((float*)d_out);
}